// round 4
// baseline (speedup 1.0000x reference)
#include <cuda_runtime.h>
#include <cstdint>

#define N_MAX 65536
#define M_IND 1024
#define KNN 16

// Scratch (static device globals — no allocation allowed)
__device__ unsigned g_idx[N_MAX * KNN];        // selected neighbor indices
__device__ float    g_Su[M_IND * M_IND];       // Su = Lu Lu^T

// ---------------------------------------------------------------------------
// Kernel 1: Su = Lu Lu^T, Lu = tril(raw,-1) + diag(exp(diag(raw)))
// ---------------------------------------------------------------------------
__global__ void su_kernel(const float* __restrict__ raw) {
    int bj = blockIdx.x, bi = blockIdx.y;
    if (bj > bi) return;
    __shared__ float At[16][68];
    __shared__ float Bt[16][68];
    int tid = threadIdx.x;           // 256 threads
    int tx = tid & 15, ty = tid >> 4;
    int lr = tid >> 2;
    int lk = (tid & 3) << 2;
    int rA = bi << 6, rB = bj << 6;
    int nk = (bj + 1) << 6;

    float acc[4][4];
#pragma unroll
    for (int u = 0; u < 4; u++)
#pragma unroll
        for (int v = 0; v < 4; v++) acc[u][v] = 0.0f;

    for (int kc = 0; kc < nk; kc += 16) {
        int ga = rA + lr;
        float4 va = *(const float4*)(raw + (size_t)ga * M_IND + kc + lk);
        int gb = rB + lr;
        float4 vb = *(const float4*)(raw + (size_t)gb * M_IND + kc + lk);
        float a4[4] = {va.x, va.y, va.z, va.w};
        float b4[4] = {vb.x, vb.y, vb.z, vb.w};
#pragma unroll
        for (int u = 0; u < 4; u++) {
            int gc = kc + lk + u;
            float x = a4[u];
            At[lk + u][lr] = (gc < ga) ? x : ((gc == ga) ? expf(x) : 0.0f);
            float y = b4[u];
            Bt[lk + u][lr] = (gc < gb) ? y : ((gc == gb) ? expf(y) : 0.0f);
        }
        __syncthreads();
#pragma unroll
        for (int kk = 0; kk < 16; kk++) {
            float4 a = *(const float4*)&At[kk][ty << 2];
            float4 b = *(const float4*)&Bt[kk][tx << 2];
            float aa[4] = {a.x, a.y, a.z, a.w};
            float bb[4] = {b.x, b.y, b.z, b.w};
#pragma unroll
            for (int u = 0; u < 4; u++)
#pragma unroll
                for (int v = 0; v < 4; v++)
                    acc[u][v] = fmaf(aa[u], bb[v], acc[u][v]);
        }
        __syncthreads();
    }
#pragma unroll
    for (int u = 0; u < 4; u++)
#pragma unroll
        for (int v = 0; v < 4; v++) {
            int gi = rA + (ty << 2) + u;
            int gj = rB + (tx << 2) + v;
            g_Su[(size_t)gi * M_IND + gj] = acc[u][v];
            g_Su[(size_t)gj * M_IND + gi] = acc[u][v];
        }
}

// ---------------------------------------------------------------------------
// Kernel 2: per-point EXACT 16-NN, 3 passes.
//  A) quantized 32-bit composite keys -> boundary bucket B (fast replace-max)
//  B) rescan: buffer all candidates with trunc(d2) <= B as exact u64 keys
//  C) exact u64 replace-max over the small buffer (~16-20 entries)
// Pass A invariant (monotone truncation): every true top-16 member has
// trunc(d2bits) <= B, so pass B's filter is lossless.
// ---------------------------------------------------------------------------
__global__ void topk_kernel(const float* __restrict__ X,
                            const float* __restrict__ Z, int N) {
    __shared__ float4 zs[M_IND];
    for (int t = threadIdx.x; t < M_IND; t += blockDim.x) {
        float a = Z[3 * t], b = Z[3 * t + 1], c = Z[3 * t + 2];
        zs[t] = make_float4(a, b, c, fmaf(a, a, fmaf(b, b, c * c)));
    }
    __syncthreads();
    int p = blockIdx.x * blockDim.x + threadIdx.x;
    if (p >= N) return;
    float x0 = X[3 * p], x1 = X[3 * p + 1], x2 = X[3 * p + 2];
    float xs = fmaf(x0, x0, fmaf(x1, x1, x2 * x2));
    float n0 = -2.0f * x0, n1 = -2.0f * x1, n2 = -2.0f * x2;

    // ---- Pass A: quantized composite keys, learn boundary bucket ----
    unsigned ks[KNN];
#pragma unroll
    for (int s = 0; s < KNN; s++) {
        float4 z = zs[s];
        float d = fmaxf(fmaf(n0, z.x, fmaf(n1, z.y, fmaf(n2, z.z, xs + z.w))), 0.0f);
        ks[s] = (__float_as_uint(d) & 0xFFFFFC00u) | (unsigned)s;
    }
    unsigned kmax = ks[0];
#pragma unroll
    for (int s = 1; s < KNN; s++) kmax = max(kmax, ks[s]);

#pragma unroll 4
    for (int i = KNN; i < M_IND; i++) {
        float4 z = zs[i];
        float d = fmaxf(fmaf(n0, z.x, fmaf(n1, z.y, fmaf(n2, z.z, xs + z.w))), 0.0f);
        unsigned key = (__float_as_uint(d) & 0xFFFFFC00u) | (unsigned)i;
        if (key < kmax) {
#pragma unroll
            for (int s = 0; s < KNN; s++) ks[s] = (ks[s] == kmax) ? key : ks[s];
            unsigned m = ks[0];
#pragma unroll
            for (int s = 1; s < KNN; s++) m = max(m, ks[s]);
            kmax = m;
        }
    }
    unsigned B = kmax & 0xFFFFFC00u;

    // ---- Pass B: buffer exact keys of boundary-feasible candidates ----
    unsigned long long buf[32];
    int c = 0;
#pragma unroll 4
    for (int i = 0; i < M_IND; i++) {
        float4 z = zs[i];
        float d = fmaxf(fmaf(n0, z.x, fmaf(n1, z.y, fmaf(n2, z.z, xs + z.w))), 0.0f);
        unsigned db = __float_as_uint(d);
        if ((db & 0xFFFFFC00u) <= B) {
            if (c < 32)
                buf[c] = ((unsigned long long)db << 32) | (unsigned)i;
            c++;
        }
    }
    if (c > 32) c = 32;  // pathological mass-tie fallback (never expected)

    // ---- Pass C: exact u64 selection over the small buffer ----
    unsigned long long ks2[KNN];
#pragma unroll
    for (int s = 0; s < KNN; s++)
        ks2[s] = 0xFFFFFFFF00000000ull | (unsigned)s;   // unique sentinels
    unsigned long long kmax2 = 0xFFFFFFFF0000000Full;
    for (int j = 0; j < c; j++) {
        unsigned long long key = buf[j];
        if (key < kmax2) {
#pragma unroll
            for (int s = 0; s < KNN; s++) ks2[s] = (ks2[s] == kmax2) ? key : ks2[s];
            unsigned long long m = ks2[0];
#pragma unroll
            for (int s = 1; s < KNN; s++) m = max(m, ks2[s]);
            kmax2 = m;
        }
    }

    unsigned idx16[KNN];
#pragma unroll
    for (int s = 0; s < KNN; s++) idx16[s] = (unsigned)(ks2[s] & 0xFFFFFFFFu);
    uint4* o = (uint4*)(g_idx + (size_t)p * KNN);
    o[0] = make_uint4(idx16[0], idx16[1], idx16[2], idx16[3]);
    o[1] = make_uint4(idx16[4], idx16[5], idx16[6], idx16[7]);
    o[2] = make_uint4(idx16[8], idx16[9], idx16[10], idx16[11]);
    o[3] = make_uint4(idx16[12], idx16[13], idx16[14], idx16[15]);
}

// ---------------------------------------------------------------------------
// Kernel 3: half-warp per point, fully register-resident fp64 Gauss-Jordan.
// Lane l owns row l of [A | rhs]; pivot rows broadcast via width-16 shuffles.
// ---------------------------------------------------------------------------
__global__ void solve_kernel(const float* __restrict__ X,
                             const float* __restrict__ Z,
                             const float* __restrict__ mu,
                             float* __restrict__ out, int N) {
    const unsigned FULL = 0xFFFFFFFFu;
    int lane = threadIdx.x & 31;
    int half = lane >> 4;
    int l = lane & 15;
    int p = (blockIdx.x << 4) + ((threadIdx.x >> 5) << 1) + half;
    int pc = p < N ? p : N - 1;

    float x0 = X[3 * pc], x1 = X[3 * pc + 1], x2 = X[3 * pc + 2];
    float xs = fmaf(x0, x0, fmaf(x1, x1, x2 * x2));

    unsigned idxv = g_idx[(size_t)pc * KNN + l];
    float zx = Z[3 * idxv], zy = Z[3 * idxv + 1], zz = Z[3 * idxv + 2];
    float z2 = fmaf(zx, zx, fmaf(zy, zy, zz * zz));
    float d2r = fmaxf(xs + z2 - 2.0f * fmaf(x0, zx, fmaf(x1, zy, x2 * zz)), 0.0f);
    double muv = (double)mu[idxv];

    double a[17];
    a[16] = (double)expf(-0.5f * d2r);   // rhs = lKxz

    // Build row l of A = lKzz + 2e-4 I (recomputed from Z coords)
#pragma unroll
    for (int i = 0; i < 16; i++) {
        float zxi = __shfl_sync(FULL, zx, i, 16);
        float zyi = __shfl_sync(FULL, zy, i, 16);
        float zzi = __shfl_sync(FULL, zz, i, 16);
        float dx = zxi - zx, dy = zyi - zy, dz = zzi - zz;
        float d2 = fmaf(dx, dx, fmaf(dy, dy, dz * dz));
        a[i] = (i == l) ? (1.0 + 2e-4) : (double)expf(-0.5f * d2);
    }

    // Gauss-Jordan, fully unrolled, register-resident
#pragma unroll
    for (int k = 0; k < 16; k++) {
        double piv = __shfl_sync(FULL, a[k], k, 16);
        double rp = 1.0 / piv;
        double f = (l == k) ? 0.0 : a[k] * rp;
#pragma unroll
        for (int cc = k + 1; cc <= 16; cc++) {
            double bc = __shfl_sync(FULL, a[cc], k, 16);
            a[cc] = fma(-f, bc, a[cc]);
        }
    }
    double diag = a[0];
#pragma unroll
    for (int cc = 1; cc < 16; cc++) if (l == cc) diag = a[cc];
    double Wv = a[16] / diag;

    // cov = 1 + sum_ij W_i W_j (Su_ij - lKzz_ij); lKzz diag = 1 + 1e-4
    double acc = 0.0;
#pragma unroll
    for (int i = 0; i < 16; i++) {
        double Wi = __shfl_sync(FULL, Wv, i, 16);
        unsigned ia = __shfl_sync(FULL, idxv, i, 16);
        float su = g_Su[(size_t)ia * M_IND + idxv];
        float zxi = __shfl_sync(FULL, zx, i, 16);
        float zyi = __shfl_sync(FULL, zy, i, 16);
        float zzi = __shfl_sync(FULL, zz, i, 16);
        float dx = zxi - zx, dy = zyi - zy, dz = zzi - zz;
        float d2 = fmaf(dx, dx, fmaf(dy, dy, dz * dz));
        float kv = (i == l) ? 1.0001f : expf(-0.5f * d2);
        acc = fma(Wi * Wv, (double)su - (double)kv, acc);
    }
    double mpart = Wv * muv;
#pragma unroll
    for (int o = 8; o > 0; o >>= 1) {
        acc   += __shfl_xor_sync(FULL, acc, o, 16);
        mpart += __shfl_xor_sync(FULL, mpart, o, 16);
    }
    if (l == 0 && p < N) {
        out[p] = (float)mpart;                         // mean
        float cov = (float)(1.0 + acc);
        out[N + p] = sqrtf(fmaxf(cov, 0.05f));         // std
    }
}

// ---------------------------------------------------------------------------
extern "C" void kernel_launch(void* const* d_in, const int* in_sizes, int n_in,
                              void* d_out, int out_size) {
    const float* X      = (const float*)d_in[0];
    const float* Z      = (const float*)d_in[1];
    const float* Lu_raw = (const float*)d_in[2];
    const float* mu     = (const float*)d_in[3];
    float* out = (float*)d_out;
    int N = in_sizes[0] / 3;

    su_kernel<<<dim3(16, 16), 256>>>(Lu_raw);
    topk_kernel<<<(N + 127) / 128, 128>>>(X, Z, N);
    solve_kernel<<<(N + 15) / 16, 256>>>(X, Z, mu, out, N);
}

// round 5
// speedup vs baseline: 1.6357x; 1.6357x over previous
#include <cuda_runtime.h>
#include <cstdint>
#include <math_constants.h>

#define N_MAX 65536
#define M_IND 1024
#define KNN 16
#define BUFCAP 224

// Scratch (static device globals — no allocation allowed)
__device__ unsigned g_idx[N_MAX * KNN];        // selected neighbor indices
__device__ float    g_Su[M_IND * M_IND];       // Su = Lu Lu^T

// ---------------------------------------------------------------------------
// Kernel 1: Su = Lu Lu^T, Lu = tril(raw,-1) + diag(exp(diag(raw)))
// ---------------------------------------------------------------------------
__global__ void su_kernel(const float* __restrict__ raw) {
    int bj = blockIdx.x, bi = blockIdx.y;
    if (bj > bi) return;
    __shared__ float At[16][68];
    __shared__ float Bt[16][68];
    int tid = threadIdx.x;           // 256 threads
    int tx = tid & 15, ty = tid >> 4;
    int lr = tid >> 2;
    int lk = (tid & 3) << 2;
    int rA = bi << 6, rB = bj << 6;
    int nk = (bj + 1) << 6;

    float acc[4][4];
#pragma unroll
    for (int u = 0; u < 4; u++)
#pragma unroll
        for (int v = 0; v < 4; v++) acc[u][v] = 0.0f;

    for (int kc = 0; kc < nk; kc += 16) {
        int ga = rA + lr;
        float4 va = *(const float4*)(raw + (size_t)ga * M_IND + kc + lk);
        int gb = rB + lr;
        float4 vb = *(const float4*)(raw + (size_t)gb * M_IND + kc + lk);
        float a4[4] = {va.x, va.y, va.z, va.w};
        float b4[4] = {vb.x, vb.y, vb.z, vb.w};
#pragma unroll
        for (int u = 0; u < 4; u++) {
            int gc = kc + lk + u;
            float x = a4[u];
            At[lk + u][lr] = (gc < ga) ? x : ((gc == ga) ? expf(x) : 0.0f);
            float y = b4[u];
            Bt[lk + u][lr] = (gc < gb) ? y : ((gc == gb) ? expf(y) : 0.0f);
        }
        __syncthreads();
#pragma unroll
        for (int kk = 0; kk < 16; kk++) {
            float4 a = *(const float4*)&At[kk][ty << 2];
            float4 b = *(const float4*)&Bt[kk][tx << 2];
            float aa[4] = {a.x, a.y, a.z, a.w};
            float bb[4] = {b.x, b.y, b.z, b.w};
#pragma unroll
            for (int u = 0; u < 4; u++)
#pragma unroll
                for (int v = 0; v < 4; v++)
                    acc[u][v] = fmaf(aa[u], bb[v], acc[u][v]);
        }
        __syncthreads();
    }
#pragma unroll
    for (int u = 0; u < 4; u++)
#pragma unroll
        for (int v = 0; v < 4; v++) {
            int gi = rA + (ty << 2) + u;
            int gj = rB + (tx << 2) + v;
            g_Su[(size_t)gi * M_IND + gj] = acc[u][v];
            g_Su[(size_t)gj * M_IND + gi] = acc[u][v];
        }
}

// ---------------------------------------------------------------------------
// Kernel 2: per-point EXACT 16-NN.
//  Phase 1: stride-8 sample (128), branchless sorted bubble -> T0 = sample
//           16th-smallest d2. Valid threshold: global 16th <= T0.
//  Phase 2: full scan, predicated store of exact u64 (d2bits<<32|idx) keys
//           for d2 <= T0 into 224-entry local buffer (no branches).
//  Phase 3: exact u64 replace-max over the ~128 buffered keys.
//  Overflow fallback: full exact u64 scan (never expected).
// ---------------------------------------------------------------------------
__global__ void topk_kernel(const float* __restrict__ X,
                            const float* __restrict__ Z, int N) {
    __shared__ float4 zs[M_IND];
    for (int t = threadIdx.x; t < M_IND; t += blockDim.x) {
        float a = Z[3 * t], b = Z[3 * t + 1], c = Z[3 * t + 2];
        zs[t] = make_float4(a, b, c, fmaf(a, a, fmaf(b, b, c * c)));
    }
    __syncthreads();
    int p = blockIdx.x * blockDim.x + threadIdx.x;
    if (p >= N) return;
    float x0 = X[3 * p], x1 = X[3 * p + 1], x2 = X[3 * p + 2];
    float xs = fmaf(x0, x0, fmaf(x1, x1, x2 * x2));
    float n0 = -2.0f * x0, n1 = -2.0f * x1, n2 = -2.0f * x2;

    // ---- Phase 1: sampled threshold via branchless sorted bubble ----
    float ks[KNN];
#pragma unroll
    for (int s = 0; s < KNN; s++) ks[s] = CUDART_INF_F;
#pragma unroll 2
    for (int i = 0; i < M_IND; i += 8) {
        float4 z = zs[i];
        float t = fmaxf(fmaf(n0, z.x, fmaf(n1, z.y, fmaf(n2, z.z, xs + z.w))), 0.0f);
#pragma unroll
        for (int s = 0; s < KNN; s++) {
            float lo = fminf(ks[s], t);
            float hi = fmaxf(ks[s], t);
            ks[s] = lo; t = hi;
        }
    }
    unsigned T0 = __float_as_uint(ks[KNN - 1]);  // sample 16th smallest (bits)

    // ---- Phase 2: predicated buffering of exact keys ----
    unsigned long long buf[BUFCAP];
    int c = 0;
#pragma unroll 4
    for (int i = 0; i < M_IND; i++) {
        float4 z = zs[i];
        float d = fmaxf(fmaf(n0, z.x, fmaf(n1, z.y, fmaf(n2, z.z, xs + z.w))), 0.0f);
        unsigned db = __float_as_uint(d);
        bool take = (db <= T0);
        int w = c < BUFCAP ? c : BUFCAP - 1;
        if (take) buf[w] = ((unsigned long long)db << 32) | (unsigned)i;
        c += take ? 1 : 0;
    }

    // ---- Phase 3: exact selection ----
    unsigned long long ks2[KNN];
#pragma unroll
    for (int s = 0; s < KNN; s++)
        ks2[s] = 0xFFFFFFFF00000000ull | (unsigned)s;   // unique sentinels
    unsigned long long kmax2 = 0xFFFFFFFF0000000Full;

    if (c <= BUFCAP) {
        for (int j = 0; j < c; j++) {
            unsigned long long key = buf[j];
            if (key < kmax2) {
#pragma unroll
                for (int s = 0; s < KNN; s++) ks2[s] = (ks2[s] == kmax2) ? key : ks2[s];
                unsigned long long m = ks2[0];
#pragma unroll
                for (int s = 1; s < KNN; s++) m = max(m, ks2[s]);
                kmax2 = m;
            }
        }
    } else {
        // fallback: full exact scan (pathological, ~never)
        for (int i = 0; i < M_IND; i++) {
            float4 z = zs[i];
            float d = fmaxf(fmaf(n0, z.x, fmaf(n1, z.y, fmaf(n2, z.z, xs + z.w))), 0.0f);
            unsigned long long key =
                ((unsigned long long)__float_as_uint(d) << 32) | (unsigned)i;
            if (key < kmax2) {
#pragma unroll
                for (int s = 0; s < KNN; s++) ks2[s] = (ks2[s] == kmax2) ? key : ks2[s];
                unsigned long long m = ks2[0];
#pragma unroll
                for (int s = 1; s < KNN; s++) m = max(m, ks2[s]);
                kmax2 = m;
            }
        }
    }

    unsigned idx16[KNN];
#pragma unroll
    for (int s = 0; s < KNN; s++) idx16[s] = (unsigned)(ks2[s] & 0xFFFFFFFFu);
    uint4* o = (uint4*)(g_idx + (size_t)p * KNN);
    o[0] = make_uint4(idx16[0], idx16[1], idx16[2], idx16[3]);
    o[1] = make_uint4(idx16[4], idx16[5], idx16[6], idx16[7]);
    o[2] = make_uint4(idx16[8], idx16[9], idx16[10], idx16[11]);
    o[3] = make_uint4(idx16[12], idx16[13], idx16[14], idx16[15]);
}

// ---------------------------------------------------------------------------
// Kernel 3: half-warp per point, fully register-resident fp64 Gauss-Jordan.
// ---------------------------------------------------------------------------
__global__ void solve_kernel(const float* __restrict__ X,
                             const float* __restrict__ Z,
                             const float* __restrict__ mu,
                             float* __restrict__ out, int N) {
    const unsigned FULL = 0xFFFFFFFFu;
    int lane = threadIdx.x & 31;
    int half = lane >> 4;
    int l = lane & 15;
    int p = (blockIdx.x << 4) + ((threadIdx.x >> 5) << 1) + half;
    int pc = p < N ? p : N - 1;

    float x0 = X[3 * pc], x1 = X[3 * pc + 1], x2 = X[3 * pc + 2];
    float xs = fmaf(x0, x0, fmaf(x1, x1, x2 * x2));

    unsigned idxv = g_idx[(size_t)pc * KNN + l];
    float zx = Z[3 * idxv], zy = Z[3 * idxv + 1], zz = Z[3 * idxv + 2];
    float z2 = fmaf(zx, zx, fmaf(zy, zy, zz * zz));
    float d2r = fmaxf(xs + z2 - 2.0f * fmaf(x0, zx, fmaf(x1, zy, x2 * zz)), 0.0f);
    double muv = (double)mu[idxv];

    double a[17];
    a[16] = (double)expf(-0.5f * d2r);   // rhs = lKxz

#pragma unroll
    for (int i = 0; i < 16; i++) {
        float zxi = __shfl_sync(FULL, zx, i, 16);
        float zyi = __shfl_sync(FULL, zy, i, 16);
        float zzi = __shfl_sync(FULL, zz, i, 16);
        float dx = zxi - zx, dy = zyi - zy, dz = zzi - zz;
        float d2 = fmaf(dx, dx, fmaf(dy, dy, dz * dz));
        a[i] = (i == l) ? (1.0 + 2e-4) : (double)expf(-0.5f * d2);
    }

#pragma unroll
    for (int k = 0; k < 16; k++) {
        double piv = __shfl_sync(FULL, a[k], k, 16);
        double rp = 1.0 / piv;
        double f = (l == k) ? 0.0 : a[k] * rp;
#pragma unroll
        for (int cc = k + 1; cc <= 16; cc++) {
            double bc = __shfl_sync(FULL, a[cc], k, 16);
            a[cc] = fma(-f, bc, a[cc]);
        }
    }
    double diag = a[0];
#pragma unroll
    for (int cc = 1; cc < 16; cc++) if (l == cc) diag = a[cc];
    double Wv = a[16] / diag;

    double acc = 0.0;
#pragma unroll
    for (int i = 0; i < 16; i++) {
        double Wi = __shfl_sync(FULL, Wv, i, 16);
        unsigned ia = __shfl_sync(FULL, idxv, i, 16);
        float su = g_Su[(size_t)ia * M_IND + idxv];
        float zxi = __shfl_sync(FULL, zx, i, 16);
        float zyi = __shfl_sync(FULL, zy, i, 16);
        float zzi = __shfl_sync(FULL, zz, i, 16);
        float dx = zxi - zx, dy = zyi - zy, dz = zzi - zz;
        float d2 = fmaf(dx, dx, fmaf(dy, dy, dz * dz));
        float kv = (i == l) ? 1.0001f : expf(-0.5f * d2);
        acc = fma(Wi * Wv, (double)su - (double)kv, acc);
    }
    double mpart = Wv * muv;
#pragma unroll
    for (int o = 8; o > 0; o >>= 1) {
        acc   += __shfl_xor_sync(FULL, acc, o, 16);
        mpart += __shfl_xor_sync(FULL, mpart, o, 16);
    }
    if (l == 0 && p < N) {
        out[p] = (float)mpart;                         // mean
        float cov = (float)(1.0 + acc);
        out[N + p] = sqrtf(fmaxf(cov, 0.05f));         // std
    }
}

// ---------------------------------------------------------------------------
extern "C" void kernel_launch(void* const* d_in, const int* in_sizes, int n_in,
                              void* d_out, int out_size) {
    const float* X      = (const float*)d_in[0];
    const float* Z      = (const float*)d_in[1];
    const float* Lu_raw = (const float*)d_in[2];
    const float* mu     = (const float*)d_in[3];
    float* out = (float*)d_out;
    int N = in_sizes[0] / 3;

    // topk first (also: ncu -s/-c capture lands on it for profiling)
    topk_kernel<<<(N + 127) / 128, 128>>>(X, Z, N);
    su_kernel<<<dim3(16, 16), 256>>>(Lu_raw);
    solve_kernel<<<(N + 15) / 16, 256>>>(X, Z, mu, out, N);
}

// round 6
// speedup vs baseline: 4.0920x; 2.5017x over previous
#include <cuda_runtime.h>
#include <cstdint>

#define N_MAX 65536
#define M_IND 1024
#define KNN 16
#define BUFCAP 192

// Scratch (static device globals — no allocation allowed)
__device__ unsigned g_idx[N_MAX * KNN];        // selected neighbor indices
__device__ float    g_Su[M_IND * M_IND];       // Su = Lu Lu^T

// ---------------------------------------------------------------------------
// Kernel 1: Su = Lu Lu^T, Lu = tril(raw,-1) + diag(exp(diag(raw)))
// ---------------------------------------------------------------------------
__global__ void su_kernel(const float* __restrict__ raw) {
    int bj = blockIdx.x, bi = blockIdx.y;
    if (bj > bi) return;
    __shared__ float At[16][68];
    __shared__ float Bt[16][68];
    int tid = threadIdx.x;           // 256 threads
    int tx = tid & 15, ty = tid >> 4;
    int lr = tid >> 2;
    int lk = (tid & 3) << 2;
    int rA = bi << 6, rB = bj << 6;
    int nk = (bj + 1) << 6;

    float acc[4][4];
#pragma unroll
    for (int u = 0; u < 4; u++)
#pragma unroll
        for (int v = 0; v < 4; v++) acc[u][v] = 0.0f;

    for (int kc = 0; kc < nk; kc += 16) {
        int ga = rA + lr;
        float4 va = *(const float4*)(raw + (size_t)ga * M_IND + kc + lk);
        int gb = rB + lr;
        float4 vb = *(const float4*)(raw + (size_t)gb * M_IND + kc + lk);
        float a4[4] = {va.x, va.y, va.z, va.w};
        float b4[4] = {vb.x, vb.y, vb.z, vb.w};
#pragma unroll
        for (int u = 0; u < 4; u++) {
            int gc = kc + lk + u;
            float x = a4[u];
            At[lk + u][lr] = (gc < ga) ? x : ((gc == ga) ? expf(x) : 0.0f);
            float y = b4[u];
            Bt[lk + u][lr] = (gc < gb) ? y : ((gc == gb) ? expf(y) : 0.0f);
        }
        __syncthreads();
#pragma unroll
        for (int kk = 0; kk < 16; kk++) {
            float4 a = *(const float4*)&At[kk][ty << 2];
            float4 b = *(const float4*)&Bt[kk][tx << 2];
            float aa[4] = {a.x, a.y, a.z, a.w};
            float bb[4] = {b.x, b.y, b.z, b.w};
#pragma unroll
            for (int u = 0; u < 4; u++)
#pragma unroll
                for (int v = 0; v < 4; v++)
                    acc[u][v] = fmaf(aa[u], bb[v], acc[u][v]);
        }
        __syncthreads();
    }
#pragma unroll
    for (int u = 0; u < 4; u++)
#pragma unroll
        for (int v = 0; v < 4; v++) {
            int gi = rA + (ty << 2) + u;
            int gj = rB + (tx << 2) + v;
            g_Su[(size_t)gi * M_IND + gj] = acc[u][v];
            g_Su[(size_t)gj * M_IND + gi] = acc[u][v];
        }
}

// ---------------------------------------------------------------------------
// Kernel 2: per-point EXACT 16-NN.
//  Phase 1: stride-8 sample (128). Unique composite keys
//           (d2bits & ~0x7F)|ctr, replace-max -> T0 = (kmax | 0x7F) is a
//           rounded-UP sample 16th-smallest => valid threshold.
//  Phase 2: full scan, predicated u16 idx store for d2bits <= T0 (no branch,
//           ~0.5KB local traffic/thread).
//  Phase 3: recompute exact d2 (bit-identical expr) for the ~128 candidates,
//           exact u64 (d2bits<<32|idx) replace-max.
//  Overflow fallback: full exact u64 scan.
// ---------------------------------------------------------------------------
__global__ void topk_kernel(const float* __restrict__ X,
                            const float* __restrict__ Z, int N) {
    __shared__ float4 zs[M_IND];
    for (int t = threadIdx.x; t < M_IND; t += blockDim.x) {
        float a = Z[3 * t], b = Z[3 * t + 1], c = Z[3 * t + 2];
        zs[t] = make_float4(a, b, c, fmaf(a, a, fmaf(b, b, c * c)));
    }
    __syncthreads();
    int p = blockIdx.x * blockDim.x + threadIdx.x;
    if (p >= N) return;
    float x0 = X[3 * p], x1 = X[3 * p + 1], x2 = X[3 * p + 2];
    float xs = fmaf(x0, x0, fmaf(x1, x1, x2 * x2));
    float n0 = -2.0f * x0, n1 = -2.0f * x1, n2 = -2.0f * x2;

    // ---- Phase 1: sampled threshold via replace-max on unique u32 keys ----
    unsigned ks[KNN];
#pragma unroll
    for (int s = 0; s < KNN; s++) ks[s] = 0xFFFFFF80u | (unsigned)s;
    unsigned kmax = 0xFFFFFF80u | 15u;
#pragma unroll 2
    for (int i = 0; i < M_IND; i += 8) {
        float4 z = zs[i];
        float d = fmaxf(fmaf(n0, z.x, fmaf(n1, z.y, fmaf(n2, z.z, xs + z.w))), 0.0f);
        unsigned key = (__float_as_uint(d) & 0xFFFFFF80u) | (unsigned)(i >> 3);
        if (key < kmax) {
#pragma unroll
            for (int s = 0; s < KNN; s++) ks[s] = (ks[s] == kmax) ? key : ks[s];
            unsigned m = ks[0];
#pragma unroll
            for (int s = 1; s < KNN; s++) m = max(m, ks[s]);
            kmax = m;
        }
    }
    unsigned T0 = kmax | 0x7Fu;   // >= exact sample 16th-smallest d2 bits

    // ---- Phase 2: predicated u16 index buffering ----
    unsigned short buf[BUFCAP];
    int c = 0;
#pragma unroll 4
    for (int i = 0; i < M_IND; i++) {
        float4 z = zs[i];
        float d = fmaxf(fmaf(n0, z.x, fmaf(n1, z.y, fmaf(n2, z.z, xs + z.w))), 0.0f);
        bool take = (__float_as_uint(d) <= T0);
        int w = c < BUFCAP ? c : BUFCAP - 1;
        if (take) buf[w] = (unsigned short)i;
        c += take ? 1 : 0;
    }

    // ---- Phase 3: exact u64 selection over candidates ----
    unsigned long long ks2[KNN];
#pragma unroll
    for (int s = 0; s < KNN; s++)
        ks2[s] = 0xFFFFFFFF00000000ull | (unsigned)s;   // unique sentinels
    unsigned long long kmax2 = 0xFFFFFFFF0000000Full;

    if (c <= BUFCAP) {
        for (int j = 0; j < c; j++) {
            unsigned i = buf[j];
            float4 z = zs[i];
            float d = fmaxf(fmaf(n0, z.x, fmaf(n1, z.y, fmaf(n2, z.z, xs + z.w))), 0.0f);
            unsigned long long key =
                ((unsigned long long)__float_as_uint(d) << 32) | i;
            if (key < kmax2) {
#pragma unroll
                for (int s = 0; s < KNN; s++) ks2[s] = (ks2[s] == kmax2) ? key : ks2[s];
                unsigned long long m = ks2[0];
#pragma unroll
                for (int s = 1; s < KNN; s++) m = max(m, ks2[s]);
                kmax2 = m;
            }
        }
    } else {
        for (int i = 0; i < M_IND; i++) {
            float4 z = zs[i];
            float d = fmaxf(fmaf(n0, z.x, fmaf(n1, z.y, fmaf(n2, z.z, xs + z.w))), 0.0f);
            unsigned long long key =
                ((unsigned long long)__float_as_uint(d) << 32) | (unsigned)i;
            if (key < kmax2) {
#pragma unroll
                for (int s = 0; s < KNN; s++) ks2[s] = (ks2[s] == kmax2) ? key : ks2[s];
                unsigned long long m = ks2[0];
#pragma unroll
                for (int s = 1; s < KNN; s++) m = max(m, ks2[s]);
                kmax2 = m;
            }
        }
    }

    unsigned idx16[KNN];
#pragma unroll
    for (int s = 0; s < KNN; s++) idx16[s] = (unsigned)(ks2[s] & 0xFFFFFFFFu);
    uint4* o = (uint4*)(g_idx + (size_t)p * KNN);
    o[0] = make_uint4(idx16[0], idx16[1], idx16[2], idx16[3]);
    o[1] = make_uint4(idx16[4], idx16[5], idx16[6], idx16[7]);
    o[2] = make_uint4(idx16[8], idx16[9], idx16[10], idx16[11]);
    o[3] = make_uint4(idx16[12], idx16[13], idx16[14], idx16[15]);
}

// ---------------------------------------------------------------------------
// Kernel 3: half-warp per point, register-resident fp32 Gauss-Jordan.
// (fp32 validated: R1-vs-R3 error delta bounds fp32-solve contribution <=5e-5.)
// ---------------------------------------------------------------------------
__global__ void solve_kernel(const float* __restrict__ X,
                             const float* __restrict__ Z,
                             const float* __restrict__ mu,
                             float* __restrict__ out, int N) {
    const unsigned FULL = 0xFFFFFFFFu;
    int lane = threadIdx.x & 31;
    int half = lane >> 4;
    int l = lane & 15;
    int p = (blockIdx.x << 4) + ((threadIdx.x >> 5) << 1) + half;
    int pc = p < N ? p : N - 1;

    float x0 = X[3 * pc], x1 = X[3 * pc + 1], x2 = X[3 * pc + 2];
    float xs = fmaf(x0, x0, fmaf(x1, x1, x2 * x2));

    unsigned idxv = g_idx[(size_t)pc * KNN + l];
    float zx = Z[3 * idxv], zy = Z[3 * idxv + 1], zz = Z[3 * idxv + 2];
    float z2 = fmaf(zx, zx, fmaf(zy, zy, zz * zz));
    float d2r = fmaxf(xs + z2 - 2.0f * fmaf(x0, zx, fmaf(x1, zy, x2 * zz)), 0.0f);
    float muv = mu[idxv];

    float a[17];
    a[16] = expf(-0.5f * d2r);   // rhs = lKxz

    // Build row l of A = lKzz + 2e-4 I (recomputed from Z coords)
#pragma unroll
    for (int i = 0; i < 16; i++) {
        float zxi = __shfl_sync(FULL, zx, i, 16);
        float zyi = __shfl_sync(FULL, zy, i, 16);
        float zzi = __shfl_sync(FULL, zz, i, 16);
        float dx = zxi - zx, dy = zyi - zy, dz = zzi - zz;
        float d2 = fmaf(dx, dx, fmaf(dy, dy, dz * dz));
        a[i] = (i == l) ? (1.0f + 2e-4f) : expf(-0.5f * d2);
    }

    // Gauss-Jordan, fully unrolled, register-resident
#pragma unroll
    for (int k = 0; k < 16; k++) {
        float piv = __shfl_sync(FULL, a[k], k, 16);
        float rp = 1.0f / piv;
        float f = (l == k) ? 0.0f : a[k] * rp;
#pragma unroll
        for (int cc = k + 1; cc <= 16; cc++) {
            float bc = __shfl_sync(FULL, a[cc], k, 16);
            a[cc] = fmaf(-f, bc, a[cc]);
        }
    }
    float diag = a[0];
#pragma unroll
    for (int cc = 1; cc < 16; cc++) if (l == cc) diag = a[cc];
    float Wv = a[16] / diag;

    // cov = 1 + sum_ij W_i W_j (Su_ij - lKzz_ij); lKzz diag = 1 + 1e-4
    float acc = 0.0f;
#pragma unroll
    for (int i = 0; i < 16; i++) {
        float Wi = __shfl_sync(FULL, Wv, i, 16);
        unsigned ia = __shfl_sync(FULL, idxv, i, 16);
        float su = g_Su[(size_t)ia * M_IND + idxv];
        float zxi = __shfl_sync(FULL, zx, i, 16);
        float zyi = __shfl_sync(FULL, zy, i, 16);
        float zzi = __shfl_sync(FULL, zz, i, 16);
        float dx = zxi - zx, dy = zyi - zy, dz = zzi - zz;
        float d2 = fmaf(dx, dx, fmaf(dy, dy, dz * dz));
        float kv = (i == l) ? 1.0001f : expf(-0.5f * d2);
        acc = fmaf(Wi * Wv, su - kv, acc);
    }
    float mpart = Wv * muv;
#pragma unroll
    for (int o = 8; o > 0; o >>= 1) {
        acc   += __shfl_xor_sync(FULL, acc, o, 16);
        mpart += __shfl_xor_sync(FULL, mpart, o, 16);
    }
    if (l == 0 && p < N) {
        out[p] = mpart;                                // mean
        float cov = 1.0f + acc;
        out[N + p] = sqrtf(fmaxf(cov, 0.05f));         // std
    }
}

// ---------------------------------------------------------------------------
extern "C" void kernel_launch(void* const* d_in, const int* in_sizes, int n_in,
                              void* d_out, int out_size) {
    const float* X      = (const float*)d_in[0];
    const float* Z      = (const float*)d_in[1];
    const float* Lu_raw = (const float*)d_in[2];
    const float* mu     = (const float*)d_in[3];
    float* out = (float*)d_out;
    int N = in_sizes[0] / 3;

    // topk first (ncu -s/-c capture lands on it)
    topk_kernel<<<(N + 127) / 128, 128>>>(X, Z, N);
    su_kernel<<<dim3(16, 16), 256>>>(Lu_raw);
    solve_kernel<<<(N + 15) / 16, 256>>>(X, Z, mu, out, N);
}